// round 2
// baseline (speedup 1.0000x reference)
#include <cuda_runtime.h>

// Lookahead depthwise conv:
//   out[t,b,f] = sum_{k=0..20} x[t+k,b,f] * w[f,k],  x[t+k>=S] = 0
// x: (S=2048, B=32, F=1024) fp32, w: (F=1024, 21) fp32, out same shape as x.

#define S_LEN   2048
#define NBATCH  32
#define NFEAT   1024
#define TAPS    21
#define BF      (NBATCH * NFEAT)      /* 32768 floats per t-slice */
#define PAIRS   (BF / 2)              /* 16384 f32x2 lanes per slice */
#define SPLIT   4
#define TSEG    (S_LEN / SPLIT)       /* 512 t per thread */
#define NCHUNK  (TSEG / TAPS)         /* 24 full 21-step chunks */
#define TTAIL   (TSEG - NCHUNK * TAPS)/* 8 tail steps */
#define TPB     256

typedef unsigned long long u64;

// Packed dual-fp32 ops (Blackwell, sm_100a+). ptxas never auto-fuses these;
// they double fp32 FMA throughput per issue slot vs 3-reg FFMA.
__device__ __forceinline__ u64 ffma2(u64 a, u64 b, u64 c) {
    u64 d;
    asm("fma.rn.f32x2 %0, %1, %2, %3;" : "=l"(d) : "l"(a), "l"(b), "l"(c));
    return d;
}
__device__ __forceinline__ u64 fadd2(u64 a, u64 b) {
    u64 d;
    asm("add.rn.f32x2 %0, %1, %2;" : "=l"(d) : "l"(a), "l"(b));
    return d;
}
__device__ __forceinline__ u64 pack2(float lo, float hi) {
    u64 d;
    asm("mov.b64 %0, {%1, %2};" : "=l"(d) : "f"(lo), "f"(hi));
    return d;
}

__global__ void __launch_bounds__(TPB, 2)
lookahead_kernel(const float* __restrict__ x,
                 const float* __restrict__ w,
                 float* __restrict__ out)
{
    const unsigned g = blockIdx.x * TPB + threadIdx.x;
    const unsigned p = g & (PAIRS - 1);      // (b, feature-pair) id
    const unsigned s = g >> 14;              // t-segment id (PAIRS = 2^14)
    const unsigned base = 2u * p;            // float offset within a t-slice
    const unsigned f0 = base & (NFEAT - 1);  // feature index of lane .lo

    // Per-thread packed weights: wk[k] = (w[f0][k], w[f0+1][k])
    u64 wk[TAPS];
#pragma unroll
    for (int k = 0; k < TAPS; ++k)
        wk[k] = pack2(w[f0 * TAPS + k], w[(f0 + 1) * TAPS + k]);

    const unsigned t_begin = s * TSEG;

    // Prologue: fill the 21-entry sliding window with x[t_begin .. t_begin+20].
    // Always in-bounds: max t_begin + 20 = 1556 < 2048.
    u64 xw[TAPS];
#pragma unroll
    for (int i = 0; i < TAPS; ++i)
        xw[i] = *reinterpret_cast<const u64*>(x + (t_begin + i) * BF + base);

    unsigned t   = t_begin;
    unsigned off = t_begin * BF + base;           // load/store float offset
    const unsigned AHEAD = TAPS * BF;             // refill is 21 slices ahead

    // Full 21-step chunks: ring indices (r+k)%21 are compile-time constants,
    // so the window rotates for free (no register shifts).
    for (int c = 0; c < NCHUNK; ++c) {
#pragma unroll
        for (int r = 0; r < TAPS; ++r) {
            u64 acc[3] = {0ull, 0ull, 0ull};
#pragma unroll
            for (int k = 0; k < TAPS; ++k)
                acc[k % 3] = ffma2(xw[(r + k) % TAPS], wk[k], acc[k % 3]);
            u64 sum = fadd2(fadd2(acc[0], acc[1]), acc[2]);
            *reinterpret_cast<u64*>(out + off) = sum;

            // Refill window slot r with x[t+21] (zero past the end: lookahead pad).
            u64 nv = 0ull;
            if (t + TAPS < S_LEN)
                nv = *reinterpret_cast<const u64*>(x + off + AHEAD);
            xw[r] = nv;

            ++t;
            off += BF;
        }
    }

    // Tail (TSEG % 21 = 8 outputs); refills still needed for later tail steps.
#pragma unroll
    for (int r = 0; r < TTAIL; ++r) {
        u64 acc[3] = {0ull, 0ull, 0ull};
#pragma unroll
        for (int k = 0; k < TAPS; ++k)
            acc[k % 3] = ffma2(xw[(r + k) % TAPS], wk[k], acc[k % 3]);
        u64 sum = fadd2(fadd2(acc[0], acc[1]), acc[2]);
        *reinterpret_cast<u64*>(out + off) = sum;

        u64 nv = 0ull;
        if (t + TAPS < S_LEN)
            nv = *reinterpret_cast<const u64*>(x + off + AHEAD);
        xw[r] = nv;

        ++t;
        off += BF;
    }
}

extern "C" void kernel_launch(void* const* d_in, const int* in_sizes, int n_in,
                              void* d_out, int out_size)
{
    const float* x = (const float*)d_in[0];   // (2048, 32, 1024) fp32
    const float* w = (const float*)d_in[1];   // (1024, 21) fp32
    float* out = (float*)d_out;               // (2048, 32, 1024) fp32

    const int total_threads = PAIRS * SPLIT;  // 65536
    lookahead_kernel<<<total_threads / TPB, TPB>>>(x, w, out);
}

// round 3
// speedup vs baseline: 1.1450x; 1.1450x over previous
#include <cuda_runtime.h>

// Lookahead depthwise conv (scatter form):
//   out[t,b,f] = sum_{k=0..20} x[t+k,b,f] * w[f,k],  x[t+k>=S] = 0
// Scatter: each loaded slice x[tau] updates 21 ring accumulators,
// completing out[tau-20] each step. 7-deep load pipeline -> MLP ~= 7.

#define S_LEN   2048
#define NBATCH  32
#define NFEAT   1024
#define TAPS    21
#define BF      (NBATCH * NFEAT)      /* 32768 floats per t-slice */
#define PAIRS   (BF / 2)              /* 16384 f32x2 lanes per slice */
#define SPLIT   4
#define TSEG    (S_LEN / SPLIT)       /* 512 outputs per thread */
#define PIPE    7                     /* prefetch depth; divides 21 */
#define TPB     128

typedef unsigned long long u64;

__device__ __forceinline__ u64 ffma2(u64 a, u64 b, u64 c) {
    u64 d;
    asm("fma.rn.f32x2 %0, %1, %2, %3;" : "=l"(d) : "l"(a), "l"(b), "l"(c));
    return d;
}
__device__ __forceinline__ u64 fmul2(u64 a, u64 b) {
    u64 d;
    asm("mul.rn.f32x2 %0, %1, %2;" : "=l"(d) : "l"(a), "l"(b));
    return d;
}
__device__ __forceinline__ u64 pack2(float lo, float hi) {
    u64 d;
    asm("mov.b64 %0, {%1, %2};" : "=l"(d) : "f"(lo), "f"(hi));
    return d;
}

// One scatter step. Rn must be a compile-time literal after unrolling so all
// ring indices fold to constants (registers, no local memory).
// Order: k=20 tap completes the oldest output (store), k=19..1 accumulate,
// k=0 re-initializes the freed slot with a MUL (no zero-init needed).
#define STEP(Rn, DO_STORE, DO_LOAD)                                          \
  do {                                                                       \
    const int R_ = (Rn) % TAPS;                                              \
    const int Q_ = (Rn) % PIPE;                                              \
    u64 xv_ = pipe[Q_];                                                      \
    if (DO_LOAD) {                                                           \
      u64 nv_ = 0ull;                                                        \
      if (live > 0) nv_ = *reinterpret_cast<const u64*>(ldp);                \
      --live;                                                                \
      ldp += BF;                                                             \
      pipe[Q_] = nv_;                                                        \
    }                                                                        \
    const int DONE_ = (R_ + 1) % TAPS;                                       \
    acc[DONE_] = ffma2(xv_, wk[TAPS - 1], acc[DONE_]);                       \
    if (DO_STORE) {                                                          \
      *reinterpret_cast<u64*>(stp) = acc[DONE_];                             \
      stp += BF;                                                             \
    }                                                                        \
    _Pragma("unroll")                                                        \
    for (int k_ = 1; k_ < TAPS; ++k_)                                        \
      acc[(R_ - k_ + 2 * TAPS) % TAPS] =                                     \
          ffma2(xv_, wk[k_], acc[(R_ - k_ + 2 * TAPS) % TAPS]);              \
    acc[R_] = fmul2(xv_, wk[0]);                                             \
  } while (0)

__global__ void __launch_bounds__(TPB, 4)
lookahead_kernel(const float* __restrict__ x,
                 const float* __restrict__ w,
                 float* __restrict__ out)
{
    const unsigned g = blockIdx.x * TPB + threadIdx.x;
    const unsigned p = g & (PAIRS - 1);      // (b, feature-pair) id
    const unsigned s = g >> 14;              // t-segment id (PAIRS = 2^14)
    const unsigned base = 2u * p;            // float offset within a t-slice
    const unsigned f0 = base & (NFEAT - 1);  // feature index of lane .lo

    // Per-thread packed weights: wk[k] = (w[f0][k], w[f0+1][k])
    u64 wk[TAPS];
#pragma unroll
    for (int k = 0; k < TAPS; ++k)
        wk[k] = pack2(w[f0 * TAPS + k], w[(f0 + 1) * TAPS + k]);

    const unsigned t0 = s * TSEG;
    const float* xin = x + (size_t)t0 * BF + base;

    // Prefetch pipeline: pipe[i] = x[t0+i], i=0..6 (always in bounds:
    // max t0+6 = 1542 < 2048).
    u64 pipe[PIPE];
#pragma unroll
    for (int i = 0; i < PIPE; ++i)
        pipe[i] = *reinterpret_cast<const u64*>(xin + i * BF);

    // Ring accumulators (zero-init is cheap insurance; the k=0 MUL
    // overwrites each slot before its first store anyway).
    u64 acc[TAPS];
#pragma unroll
    for (int j = 0; j < TAPS; ++j) acc[j] = 0ull;

    const float* ldp = xin + PIPE * BF;           // load target x[t0+n+7]
    float*       stp = out + (size_t)t0 * BF + base;
    int live = (int)(S_LEN - t0) - PIPE;          // loads valid while n < live

    // Chunk 0: n = 0..20. Only n==20 stores (completes out[t0]).
#pragma unroll
    for (int n = 0; n < TAPS; ++n)
        STEP(n, n == TAPS - 1, true);

    // Main: 24 chunks of 21 steps, n = 21..524. All store, all load.
    // n%21 = r and n%7 = r%7 (21 % 7 == 0), so all indices are literals.
    for (int c = 1; c < 25; ++c) {
#pragma unroll
        for (int r = 0; r < TAPS; ++r)
            STEP(r, true, true);
    }

    // Tail: n = 525..531 (7 steps). Stores out[t0+505..t0+511]; no loads.
#pragma unroll
    for (int r = 0; r < PIPE; ++r)
        STEP(r, true, false);
}

extern "C" void kernel_launch(void* const* d_in, const int* in_sizes, int n_in,
                              void* d_out, int out_size)
{
    const float* x = (const float*)d_in[0];   // (2048, 32, 1024) fp32
    const float* w = (const float*)d_in[1];   // (1024, 21) fp32
    float* out = (float*)d_out;               // (2048, 32, 1024) fp32

    const int total_threads = PAIRS * SPLIT;  // 65536
    lookahead_kernel<<<total_threads / TPB, TPB>>>(x, w, out);
}